// round 15
// baseline (speedup 1.0000x reference)
#include <cuda_runtime.h>
#include <cuda_fp16.h>
#include <math.h>
#include <stdint.h>

#define NN     6144
#define NFEAT  512
#define NHID   256
#define NCLASS 16

#define BM   128
#define BN2  256
#define CCAP 256
#define NT_GEMM 512
#define QKST 20          // QK smem row stride in uint32 (conflict-free, 16B-aligned)

// ---------------- scratch (static __device__, no allocation) ----------------
// Every array touched by 16B transactions (uint4 / float4 / cp.async-16) is
// explicitly 16B-aligned (uint2/uint32_t default to 8/4B alignment).
__device__ __align__(16) float g_adj[(size_t)NN * NN];
__device__ __align__(16) uint2 g_adj16[(size_t)NN * (NN / 2)];   // fp16 split of adj
__device__ __align__(16) float g_z15[NN * 15];
__device__ __align__(16) float g_nz[NN * 3];
__device__ __align__(16) float g_part[(size_t)4 * NN * NHID];
__device__ __align__(16) float g_xw[NN * NHID];
__device__ __align__(16) uint2 g_x16[(size_t)NN * (NFEAT / 2)];  // split(x) row-major
__device__ __align__(16) uint2 g_xwT16[(size_t)NHID * (NN / 2)]; // split(xw^T)
__device__ __align__(16) uint2 g_h16[(size_t)NN * (NHID / 2)];   // split(h) row-major
__device__ __align__(16) uint2 g_Wg1T16[NHID * (NFEAT / 2)];
__device__ __align__(16) uint2 g_WqT16[NHID * (NHID / 2)];
__device__ __align__(16) uint2 g_WkT16[NHID * (NHID / 2)];
__device__ __align__(16) uint2 g_WvT16[NHID * (NHID / 2)];
__device__ __align__(16) float g_Q[NN * NHID];
__device__ __align__(16) float g_K[NN * NHID];
__device__ __align__(16) float g_V[NN * NHID];
__device__ __align__(16) uint32_t g_Q16[(size_t)NN * (NHID / 2)]; // hi-fp16 only
__device__ __align__(16) uint32_t g_K16[(size_t)NN * (NHID / 2)];
__device__ __align__(16) float g_Xt[NN * NHID];
__device__ __align__(16) float g_Y[NN * NCLASS];
__device__ int   g_cand_cnt[NN];
__device__ int   g_cand_idx[(size_t)NN * CCAP];

// ---------------- helpers ----------------------------------------------------
__device__ __forceinline__ void cp16(uint32_t s, const void* g) {
    asm volatile("cp.async.cg.shared.global [%0], [%1], 16;" :: "r"(s), "l"(g));
}
__device__ __forceinline__ void cpcommit() { asm volatile("cp.async.commit_group;"); }
__device__ __forceinline__ void cpwait1()  { asm volatile("cp.async.wait_group 1;"); }
__device__ __forceinline__ void cpwait0()  { asm volatile("cp.async.wait_group 0;"); }

__device__ __forceinline__ uint32_t pack16(float x, float y) {
    __half2 h = __float22half2_rn(make_float2(x, y));
    return *reinterpret_cast<uint32_t*>(&h);
}
__device__ __forceinline__ void split2(float x, float y, uint32_t& hi, uint32_t& lo) {
    __half2 h = __float22half2_rn(make_float2(x, y));
    float rx = x - __half2float(__low2half(h));
    float ry = y - __half2float(__high2half(h));
    __half2 l = __float22half2_rn(make_float2(rx, ry));
    hi = *reinterpret_cast<uint32_t*>(&h);
    lo = *reinterpret_cast<uint32_t*>(&l);
}
__device__ __forceinline__ void mma16(float* c, const uint32_t* a, const uint32_t* b) {
    asm volatile(
        "mma.sync.aligned.m16n8k16.row.col.f32.f16.f16.f32 "
        "{%0,%1,%2,%3},{%4,%5,%6,%7},{%8,%9},{%0,%1,%2,%3};"
        : "+f"(c[0]), "+f"(c[1]), "+f"(c[2]), "+f"(c[3])
        : "r"(a[0]), "r"(a[1]), "r"(a[2]), "r"(a[3]), "r"(b[0]), "r"(b[1]));
}

// ---------------- z{1,2,3}: 4 rows per block, grid (NN/4, 3) ----------------
__global__ void z15_all_kernel(const float* __restrict__ a0,
                               const float* __restrict__ a1,
                               const float* __restrict__ a2,
                               const float* __restrict__ W1,
                               const float* __restrict__ W2,
                               const float* __restrict__ W3,
                               const float* __restrict__ b1,
                               const float* __restrict__ b2,
                               const float* __restrict__ b3)
{
    int i0 = blockIdx.x * 4;
    int slot = blockIdx.y;
    const float* adj = (slot == 0) ? a0 : (slot == 1) ? a1 : a2;
    const float* W   = (slot == 0) ? W1 : (slot == 1) ? W2 : W3;
    const float* b   = (slot == 0) ? b1 : (slot == 1) ? b2 : b3;
    int tid = threadIdx.x;
    float acc[5][4];
#pragma unroll
    for (int c = 0; c < 5; c++)
#pragma unroll
        for (int r = 0; r < 4; r++) acc[c][r] = 0.f;
    for (int j = tid; j < NN; j += 256) {
        const float* w = W + j * 5;
        float w0 = w[0], w1 = w[1], w2 = w[2], w3 = w[3], w4 = w[4];
#pragma unroll
        for (int r = 0; r < 4; r++) {
            float a = adj[(size_t)(i0 + r) * NN + j];
            acc[0][r] += a * w0; acc[1][r] += a * w1; acc[2][r] += a * w2;
            acc[3][r] += a * w3; acc[4][r] += a * w4;
        }
    }
    __shared__ float red[20][256];
#pragma unroll
    for (int c = 0; c < 5; c++)
#pragma unroll
        for (int r = 0; r < 4; r++) red[c * 4 + r][tid] = acc[c][r];
    __syncthreads();
    for (int s = 128; s > 0; s >>= 1) {
        if (tid < s) {
#pragma unroll
            for (int cc = 0; cc < 20; cc++) red[cc][tid] += red[cc][tid + s];
        }
        __syncthreads();
    }
    if (tid < 20) {
        int c = tid >> 2, r = tid & 3;
        g_z15[(i0 + r) * 15 + slot * 5 + c] = red[tid][0] + b[c];
    }
}

// ---------------- gate ------------------------------------------------------
__global__ void gate_kernel(const float* __restrict__ W_agg,
                            const float* __restrict__ b_agg,
                            float* __restrict__ nj_out)
{
    int i = blockIdx.x * blockDim.x + threadIdx.x;
    if (i >= NN) return;
    float z0 = b_agg[0], z1 = b_agg[1], z2 = b_agg[2];
#pragma unroll
    for (int k = 0; k < 15; k++) {
        float v = g_z15[i * 15 + k];
        z0 += v * W_agg[k * 3 + 0];
        z1 += v * W_agg[k * 3 + 1];
        z2 += v * W_agg[k * 3 + 2];
    }
    float m = fmaxf(z0, fmaxf(z1, z2));
    float e0 = expf(z0 - m), e1 = expf(z1 - m), e2 = expf(z2 - m);
    float s = e0 + e1 + e2;
    float n0 = e0 / s, n1 = e1 / s, n2 = e2 / s;
    g_nz[i * 3 + 0] = n0; g_nz[i * 3 + 1] = n1; g_nz[i * 3 + 2] = n2;
    nj_out[i * 3 + 0] = n0; nj_out[i * 3 + 1] = n1; nj_out[i * 3 + 2] = n2;
}

// ---------------- build adj (fp32 + fused fp16 split) -----------------------
__global__ void build_adj_kernel(const float* __restrict__ a0,
                                 const float* __restrict__ a1,
                                 const float* __restrict__ a2)
{
    const int total4 = NN * (NN / 4);
    int stride = gridDim.x * blockDim.x;
    for (int p = blockIdx.x * blockDim.x + threadIdx.x; p < total4; p += stride) {
        int idx = p * 4;
        int j = idx % NN;
        float4 v0 = ((const float4*)a0)[p];
        float4 v1 = ((const float4*)a1)[p];
        float4 v2 = ((const float4*)a2)[p];
        float4 r;
        r.x = g_nz[(j + 0) * 3 + 0] * v0.x + g_nz[(j + 0) * 3 + 1] * v1.x + g_nz[(j + 0) * 3 + 2] * v2.x;
        r.y = g_nz[(j + 1) * 3 + 0] * v0.y + g_nz[(j + 1) * 3 + 1] * v1.y + g_nz[(j + 1) * 3 + 2] * v2.y;
        r.z = g_nz[(j + 2) * 3 + 0] * v0.z + g_nz[(j + 2) * 3 + 1] * v1.z + g_nz[(j + 2) * 3 + 2] * v2.z;
        r.w = g_nz[(j + 3) * 3 + 0] * v0.w + g_nz[(j + 3) * 3 + 1] * v1.w + g_nz[(j + 3) * 3 + 2] * v2.w;
        ((float4*)g_adj)[p] = r;
        uint32_t h0, l0, h1, l1;
        split2(r.x, r.y, h0, l0);
        split2(r.z, r.w, h1, l1);
        ((uint4*)g_adj16)[p] = make_uint4(h0, l0, h1, l1);
    }
}

// ---------------- convert row-major fp32 -> [M][K/2] uint2 split ------------
__global__ void cvt_rm_kernel(const float* __restrict__ src, uint2* __restrict__ dst,
                              int total4)
{
    int p4 = blockIdx.x * 256 + threadIdx.x;
    if (p4 >= total4) return;
    float4 v = ((const float4*)src)[p4];
    uint32_t h0, l0, h1, l1;
    split2(v.x, v.y, h0, l0);
    split2(v.z, v.w, h1, l1);
    ((uint4*)dst)[p4] = make_uint4(h0, l0, h1, l1);
}

// ---------------- convert [K][N] fp32 -> [N][K/2] uint2 split (transpose) ---
// NOTE: smem tile row stride 33 floats -> float4 stores would be misaligned
// (132 % 16 != 0); global float4 load into regs, then SCALAR smem stores.
__global__ void cvt_tr_kernel(const float* __restrict__ src, uint2* __restrict__ dst,
                              int K, int N)
{
    __shared__ float s[32][33];
    int k0 = blockIdx.x * 32, n0 = blockIdx.y * 32;
    int t = threadIdx.x;
    int r = t >> 3, c4 = (t & 7) * 4;
    float4 v = *(const float4*)&src[(size_t)(k0 + r) * N + n0 + c4];
    s[r][c4 + 0] = v.x;
    s[r][c4 + 1] = v.y;
    s[r][c4 + 2] = v.z;
    s[r][c4 + 3] = v.w;
    __syncthreads();
    int n = t >> 3, kq = (t & 7) * 2;
#pragma unroll
    for (int j = 0; j < 2; j++) {
        int k2 = kq + j;
        uint32_t hi, lo;
        split2(s[2 * k2][n], s[2 * k2 + 1][n], hi, lo);
        dst[(size_t)(n0 + n) * (K / 2) + (k0 >> 1) + k2] = make_uint2(hi, lo);
    }
}

// ---------------- fp16 pre-split GEMM: 512 thr, block 128x256 ---------------
// A16 [M][ldA2] uint2(hi,lo); B16 [N][ldB2] uint2; chunk = 16 uint2 of k.
template<bool BIAS, bool RELU>
__device__ __forceinline__ void gemm_body16(const uint2* __restrict__ A16, int ldA2,
                                            const uint2* __restrict__ B16, int ldB2,
                                            int kOff2, int nIter,
                                            float* __restrict__ C,
                                            uint32_t* __restrict__ C16,
                                            int Nc, const float* __restrict__ bias)
{
    extern __shared__ uint2 sm2[];
    uint2* As = sm2;                    // [2][128][16]
    uint2* Bs = sm2 + 2 * 128 * 16;     // [2][256][16]

    int tid = threadIdx.x, lane = tid & 31, warp = tid >> 5;
    int g = lane >> 2, tig = lane & 3;
    int wm = (warp >> 2) * 32;
    int wn = (warp & 3) * 64;
    int rowBase = blockIdx.y * BM, colBase = blockIdx.x * BN2;

    float c[2][8][4];
#pragma unroll
    for (int mt = 0; mt < 2; mt++)
#pragma unroll
        for (int nt = 0; nt < 8; nt++)
#pragma unroll
            for (int r = 0; r < 4; r++) c[mt][nt][r] = 0.f;

    int am = tid >> 2, aq2 = (tid & 3) * 4;   // A: 128 rows x 16 uint2
    int bn = tid >> 1, bq2 = (tid & 1) * 8;   // B: 256 rows x 16 uint2

    auto loadChunk = [&](int it, int buf) {
        uint2* Asb = As + buf * 128 * 16;
        uint2* Bsb = Bs + buf * 256 * 16;
        const uint2* Ag = A16 + (size_t)(rowBase + am) * ldA2 + kOff2 + it * 16 + aq2;
        cp16((uint32_t)__cvta_generic_to_shared(Asb + am * 16 + aq2), Ag);
        cp16((uint32_t)__cvta_generic_to_shared(Asb + am * 16 + aq2 + 2), Ag + 2);
        const uint2* Bg = B16 + (size_t)(colBase + bn) * ldB2 + kOff2 + it * 16 + bq2;
#pragma unroll
        for (int i = 0; i < 4; i++)
            cp16((uint32_t)__cvta_generic_to_shared(Bsb + bn * 16 + bq2 + 2 * i), Bg + 2 * i);
        cpcommit();
    };

    loadChunk(0, 0);
    for (int it = 0; it < nIter; ++it) {
        int buf = it & 1;
        if (it + 1 < nIter) { loadChunk(it + 1, buf ^ 1); cpwait1(); }
        else cpwait0();
        __syncthreads();
        const uint2* Asb = As + buf * 128 * 16;
        const uint2* Bsb = Bs + buf * 256 * 16;
#pragma unroll
        for (int ks = 0; ks < 2; ks++) {
            int kb2 = ks * 8;
            uint32_t ah[2][4], al[2][4];
#pragma unroll
            for (int mt = 0; mt < 2; mt++) {
                int r0 = wm + mt * 16 + g;
                uint2 q0 = Asb[r0 * 16 + kb2 + tig];
                uint2 q1 = Asb[(r0 + 8) * 16 + kb2 + tig];
                uint2 q2 = Asb[r0 * 16 + kb2 + tig + 4];
                uint2 q3 = Asb[(r0 + 8) * 16 + kb2 + tig + 4];
                ah[mt][0] = q0.x; al[mt][0] = q0.y;
                ah[mt][1] = q1.x; al[mt][1] = q1.y;
                ah[mt][2] = q2.x; al[mt][2] = q2.y;
                ah[mt][3] = q3.x; al[mt][3] = q3.y;
            }
#pragma unroll
            for (int h2 = 0; h2 < 2; h2++) {
                uint32_t bh[4][2], bl[4][2];
#pragma unroll
                for (int nl = 0; nl < 4; nl++) {
                    int nc = wn + (h2 * 4 + nl) * 8 + g;
                    uint2 u0 = Bsb[nc * 16 + kb2 + tig];
                    uint2 u1 = Bsb[nc * 16 + kb2 + tig + 4];
                    bh[nl][0] = u0.x; bl[nl][0] = u0.y;
                    bh[nl][1] = u1.x; bl[nl][1] = u1.y;
                }
#pragma unroll
                for (int mt = 0; mt < 2; mt++)
#pragma unroll
                    for (int nl = 0; nl < 4; nl++) {
                        float* cc = c[mt][h2 * 4 + nl];
                        mma16(cc, ah[mt], bh[nl]);
                        mma16(cc, ah[mt], bl[nl]);
                        mma16(cc, al[mt], bh[nl]);
                    }
            }
        }
        __syncthreads();
    }

#pragma unroll
    for (int mt = 0; mt < 2; mt++) {
        int row = rowBase + wm + mt * 16 + g;
#pragma unroll
        for (int nt = 0; nt < 8; nt++) {
            int col = colBase + wn + nt * 8 + 2 * tig;
            float v0 = c[mt][nt][0], v1 = c[mt][nt][1];
            float v2 = c[mt][nt][2], v3 = c[mt][nt][3];
            if (BIAS) {
                float bb0 = bias[col], bb1 = bias[col + 1];
                v0 += bb0; v1 += bb1; v2 += bb0; v3 += bb1;
            }
            if (RELU) {
                v0 = fmaxf(v0, 0.f); v1 = fmaxf(v1, 0.f);
                v2 = fmaxf(v2, 0.f); v3 = fmaxf(v3, 0.f);
            }
            *(float2*)(C + (size_t)row * Nc + col) = make_float2(v0, v1);
            *(float2*)(C + (size_t)(row + 8) * Nc + col) = make_float2(v2, v3);
            if (C16) {
                C16[(size_t)row * (Nc / 2) + col / 2] = pack16(v0, v1);
                C16[(size_t)(row + 8) * (Nc / 2) + col / 2] = pack16(v2, v3);
            }
        }
    }
}

// split-K GEMM into partials
__global__ void __launch_bounds__(NT_GEMM)
mma_split(const uint2* __restrict__ A16, int ldA2,
          const uint2* __restrict__ B16, int ldB2,
          float* __restrict__ P, int kLen2)
{
    int kOff2 = blockIdx.z * kLen2;
    gemm_body16<false, false>(A16, ldA2, B16, ldB2, kOff2, kLen2 / 16,
                              P + (size_t)blockIdx.z * NN * NHID, nullptr, NHID, nullptr);
}

// batched QKV: blockIdx.z selects weight/bias/outputs
struct QKVArgs { const uint2* W[3]; const float* b[3]; float* C[3]; uint32_t* C16[3]; };
__global__ void __launch_bounds__(NT_GEMM)
mma_qkv(const uint2* __restrict__ A16, QKVArgs args)
{
    int z = blockIdx.z;
    gemm_body16<true, false>(A16, NHID / 2, args.W[z], NHID / 2, 0, (NHID / 2) / 16,
                             args.C[z], args.C16[z], NHID, args.b[z]);
}

// ---------------- combine split-K partials (+bias)(+relu)(+fp16 out) --------
template<int NP, bool BIAS, bool RELU, bool OUT16>
__global__ void combine_kernel(const float* __restrict__ P,
                               const float* __restrict__ bias,
                               float* __restrict__ out,
                               uint2* __restrict__ out16)
{
    int p4 = blockIdx.x * 256 + threadIdx.x;
    float4 v = ((const float4*)P)[p4];
#pragma unroll
    for (int z = 1; z < NP; z++) {
        float4 b = ((const float4*)(P + (size_t)z * NN * NHID))[p4];
        v.x += b.x; v.y += b.y; v.z += b.z; v.w += b.w;
    }
    if (BIAS) {
        int n = (p4 & 63) * 4;
        float4 bb = *(const float4*)(bias + n);
        v.x += bb.x; v.y += bb.y; v.z += bb.z; v.w += bb.w;
    }
    if (RELU) {
        v.x = fmaxf(v.x, 0.f); v.y = fmaxf(v.y, 0.f);
        v.z = fmaxf(v.z, 0.f); v.w = fmaxf(v.w, 0.f);
    }
    if (OUT16) {
        uint32_t h0, l0, h1, l1;
        split2(v.x, v.y, h0, l0);
        split2(v.z, v.w, h1, l1);
        ((uint4*)out16)[p4] = make_uint4(h0, l0, h1, l1);
    } else {
        ((float4*)out)[p4] = v;
    }
}

// ---------------- single-fp16 QK^T screening (pre-packed Q16/K16) -----------
__global__ void __launch_bounds__(NT_GEMM)
mma_qk(const uint32_t* __restrict__ Q16, const uint32_t* __restrict__ K16)
{
    extern __shared__ uint32_t sm1[];
    uint32_t* As = sm1;                     // [2][128][QKST]
    uint32_t* Ks = sm1 + 2 * 128 * QKST;    // [2][256][QKST]

    int tid = threadIdx.x, lane = tid & 31, warp = tid >> 5;
    int g = lane >> 2, tig = lane & 3;
    int wm = (warp >> 2) * 32;
    int wn = (warp & 3) * 64;
    int rowBase = blockIdx.y * BM, colBase = blockIdx.x * BN2;

    float c[2][8][4];
#pragma unroll
    for (int mt = 0; mt < 2; mt++)
#pragma unroll
        for (int nt = 0; nt < 8; nt++)
#pragma unroll
            for (int r = 0; r < 4; r++) c[mt][nt][r] = 0.f;

    int am = tid >> 2, aq = (tid & 3) * 4;   // A: 128 x 16 uint32
    int bn = tid >> 1, bq = (tid & 1) * 8;   // B: 256 x 16 uint32

    auto loadChunk = [&](int it, int buf) {
        uint32_t* Asb = As + buf * 128 * QKST;
        uint32_t* Ksb = Ks + buf * 256 * QKST;
        cp16((uint32_t)__cvta_generic_to_shared(Asb + am * QKST + aq),
             Q16 + (size_t)(rowBase + am) * (NHID / 2) + it * 16 + aq);
        const uint32_t* Kg = K16 + (size_t)(colBase + bn) * (NHID / 2) + it * 16 + bq;
        cp16((uint32_t)__cvta_generic_to_shared(Ksb + bn * QKST + bq), Kg);
        cp16((uint32_t)__cvta_generic_to_shared(Ksb + bn * QKST + bq + 4), Kg + 4);
        cpcommit();
    };

    const int nIter = (NHID / 2) / 16;   // 8
    loadChunk(0, 0);
    for (int it = 0; it < nIter; ++it) {
        int buf = it & 1;
        if (it + 1 < nIter) { loadChunk(it + 1, buf ^ 1); cpwait1(); }
        else cpwait0();
        __syncthreads();
        const uint32_t* Asb = As + buf * 128 * QKST;
        const uint32_t* Ksb = Ks + buf * 256 * QKST;
#pragma unroll
        for (int ks = 0; ks < 2; ks++) {
            int kb = ks * 8;
            uint32_t ah[2][4];
#pragma unroll
            for (int mt = 0; mt < 2; mt++) {
                int r0 = wm + mt * 16 + g;
                ah[mt][0] = Asb[r0 * QKST + kb + tig];
                ah[mt][1] = Asb[(r0 + 8) * QKST + kb + tig];
                ah[mt][2] = Asb[r0 * QKST + kb + tig + 4];
                ah[mt][3] = Asb[(r0 + 8) * QKST + kb + tig + 4];
            }
#pragma unroll
            for (int h2 = 0; h2 < 2; h2++) {
                uint32_t bh[4][2];
#pragma unroll
                for (int nl = 0; nl < 4; nl++) {
                    int nc = wn + (h2 * 4 + nl) * 8 + g;
                    bh[nl][0] = Ksb[nc * QKST + kb + tig];
                    bh[nl][1] = Ksb[nc * QKST + kb + tig + 4];
                }
#pragma unroll
                for (int mt = 0; mt < 2; mt++)
#pragma unroll
                    for (int nl = 0; nl < 4; nl++)
                        mma16(c[mt][h2 * 4 + nl], ah[mt], bh[nl]);
            }
        }
        __syncthreads();
    }

    // ---- epilogue: mask, per-row tile max, emit candidates ----
#pragma unroll
    for (int mt = 0; mt < 2; mt++) {
        int row = rowBase + wm + mt * 16 + g;
#pragma unroll
        for (int nt = 0; nt < 8; nt++) {
            int col = colBase + wn + nt * 8 + 2 * tig;
            float2 m0 = *(const float2*)(g_adj + (size_t)row * NN + col);
            float2 m1 = *(const float2*)(g_adj + (size_t)(row + 8) * NN + col);
            c[mt][nt][0] *= m0.x; c[mt][nt][1] *= m0.y;
            c[mt][nt][2] *= m1.x; c[mt][nt][3] *= m1.y;
        }
    }
    float lm0[2], lm1[2];
#pragma unroll
    for (int mt = 0; mt < 2; mt++) {
        float a = -1e30f, b = -1e30f;
#pragma unroll
        for (int nt = 0; nt < 8; nt++) {
            a = fmaxf(a, fmaxf(c[mt][nt][0], c[mt][nt][1]));
            b = fmaxf(b, fmaxf(c[mt][nt][2], c[mt][nt][3]));
        }
        lm0[mt] = a; lm1[mt] = b;
    }
#pragma unroll
    for (int mt = 0; mt < 2; mt++) {
        lm0[mt] = fmaxf(lm0[mt], __shfl_xor_sync(0xffffffffu, lm0[mt], 1));
        lm0[mt] = fmaxf(lm0[mt], __shfl_xor_sync(0xffffffffu, lm0[mt], 2));
        lm1[mt] = fmaxf(lm1[mt], __shfl_xor_sync(0xffffffffu, lm1[mt], 1));
        lm1[mt] = fmaxf(lm1[mt], __shfl_xor_sync(0xffffffffu, lm1[mt], 2));
    }
    float* smax = (float*)sm1;     // reuse: [128][4]
    int q = warp & 3;
    if (tig == 0) {
#pragma unroll
        for (int mt = 0; mt < 2; mt++) {
            smax[(wm + mt * 16 + g) * 4 + q] = lm0[mt];
            smax[(wm + mt * 16 + 8 + g) * 4 + q] = lm1[mt];
        }
    }
    __syncthreads();
#pragma unroll
    for (int mt = 0; mt < 2; mt++) {
#pragma unroll
        for (int half = 0; half < 2; half++) {
            int rl = wm + mt * 16 + half * 8 + g;
            float tm = fmaxf(fmaxf(smax[rl * 4 + 0], smax[rl * 4 + 1]),
                             fmaxf(smax[rl * 4 + 2], smax[rl * 4 + 3]));
            float thr = tm - 120.0f;
            int rowG = rowBase + rl;
#pragma unroll
            for (int nt = 0; nt < 8; nt++) {
#pragma unroll
                for (int j = 0; j < 2; j++) {
                    float v = c[mt][nt][half * 2 + j];
                    if (v > thr) {
                        int slot = atomicAdd(&g_cand_cnt[rowG], 1);
                        if (slot < CCAP)
                            g_cand_idx[(size_t)rowG * CCAP + slot] =
                                colBase + wn + nt * 8 + 2 * tig + j;
                    }
                }
            }
        }
    }
}

// ---------------- sparse attention: exact recompute + softmax + apply -------
__global__ void sparse_attn_kernel()
{
    __shared__ float qrow[NHID];
    __shared__ int   ci[CCAP];
    __shared__ float cv[CCAP];
    __shared__ float red[256];
    __shared__ float sw[CCAP];
    __shared__ int   sidx[CCAP];
    __shared__ int   scnt;
    int i = blockIdx.x;
    int tid = threadIdx.x;
    int warp = tid >> 5, lane = tid & 31;
    int cnt = g_cand_cnt[i];
    if (cnt > CCAP) cnt = CCAP;
    qrow[tid] = g_Q[(size_t)i * NHID + tid];
    if (tid < cnt) ci[tid] = g_cand_idx[(size_t)i * CCAP + tid];
    if (tid == 0) scnt = 0;
    __syncthreads();
    for (int c = warp; c < cnt; c += 8) {
        const float* kr = g_K + (size_t)ci[c] * NHID;
        float s = 0.f;
#pragma unroll
        for (int k = lane; k < NHID; k += 32) s += qrow[k] * kr[k];
#pragma unroll
        for (int o = 16; o > 0; o >>= 1) s += __shfl_xor_sync(0xffffffffu, s, o);
        if (lane == 0) cv[c] = s * g_adj[(size_t)i * NN + ci[c]];
    }
    __syncthreads();
    float m = (tid < cnt) ? cv[tid] : -1e30f;
    red[tid] = m;
    __syncthreads();
    for (int s = 128; s > 0; s >>= 1) {
        if (tid < s) red[tid] = fmaxf(red[tid], red[tid + s]);
        __syncthreads();
    }
    m = red[0];
    __syncthreads();
    float e = (tid < cnt) ? expf(cv[tid] - m) : 0.f;
    red[tid] = e;
    __syncthreads();
    for (int s = 128; s > 0; s >>= 1) {
        if (tid < s) red[tid] += red[tid + s];
        __syncthreads();
    }
    float inv = 1.0f / red[0];
    if (tid < cnt && cv[tid] - m > -25.f) {
        int sl = atomicAdd(&scnt, 1);
        sw[sl] = expf(cv[tid] - m) * inv;
        sidx[sl] = ci[tid];
    }
    __syncthreads();
    int ns = scnt;
    float acc = 0.f;
    for (int e2 = 0; e2 < ns; e2++)
        acc += sw[e2] * g_V[(size_t)sidx[e2] * NHID + tid];
    g_Xt[(size_t)i * NHID + tid] = fmaxf(acc, 0.f);
}

// ---------------- Y = Xt @ W_g2  (warp per row) -----------------------------
__global__ void y_kernel(const float* __restrict__ Wg2)
{
    __shared__ float Ws[NHID * NCLASS];
    int tid = threadIdx.x;
    for (int t = tid; t < NHID * NCLASS / 4; t += 256)
        ((float4*)Ws)[t] = ((const float4*)Wg2)[t];
    __syncthreads();
    int warp = tid >> 5, lane = tid & 31;
    int i = blockIdx.x * 8 + warp;
    float acc[16];
#pragma unroll
    for (int c = 0; c < 16; c++) acc[c] = 0.f;
    const float* xr = g_Xt + (size_t)i * NHID;
    for (int g = lane; g < NHID; g += 32) {
        float x = xr[g];
#pragma unroll
        for (int c = 0; c < 16; c++) acc[c] += x * Ws[g * 16 + c];
    }
#pragma unroll
    for (int c = 0; c < 16; c++)
#pragma unroll
        for (int o = 16; o > 0; o >>= 1)
            acc[c] += __shfl_xor_sync(0xffffffffu, acc[c], o);
    if (lane < 16) g_Y[i * 16 + lane] = acc[lane];
}

// ---------------- out = softmax(adj @ Y + b_g2)  (warp per row) -------------
__global__ void final_kernel(const float* __restrict__ b_g2,
                             float* __restrict__ out)
{
    __shared__ float Ys[512 * 16];
    int tid = threadIdx.x;
    int warp = tid >> 5, lane = tid & 31;
    int i = blockIdx.x * 8 + warp;
    float acc[16];
#pragma unroll
    for (int c = 0; c < 16; c++) acc[c] = 0.f;
    const float* arow = g_adj + (size_t)i * NN;
    for (int j0 = 0; j0 < NN; j0 += 512) {
        __syncthreads();
        for (int t = tid; t < 512 * 16 / 4; t += 256)
            ((float4*)Ys)[t] = ((const float4*)(g_Y + j0 * 16))[t];
        __syncthreads();
        for (int jj = lane; jj < 512; jj += 32) {
            float a = arow[j0 + jj];
#pragma unroll
            for (int c = 0; c < 16; c++) acc[c] += a * Ys[jj * 16 + c];
        }
    }
#pragma unroll
    for (int c = 0; c < 16; c++)
#pragma unroll
        for (int o = 16; o > 0; o >>= 1)
            acc[c] += __shfl_xor_sync(0xffffffffu, acc[c], o);
    if (lane == 0) {
        float z[16], m = -1e30f;
#pragma unroll
        for (int c = 0; c < 16; c++) { z[c] = acc[c] + b_g2[c]; m = fmaxf(m, z[c]); }
        float s = 0.f, e[16];
#pragma unroll
        for (int c = 0; c < 16; c++) { e[c] = expf(z[c] - m); s += e[c]; }
#pragma unroll
        for (int c = 0; c < 16; c++) out[i * 16 + c] = e[c] / s;
    }
}

// ---------------- launcher ---------------------------------------------------
extern "C" void kernel_launch(void* const* d_in, const int* in_sizes, int n_in,
                              void* d_out, int out_size)
{
    const float* adj0  = (const float*)d_in[0];
    const float* adj1  = (const float*)d_in[1];
    const float* adj2  = (const float*)d_in[2];
    const float* x     = (const float*)d_in[3];
    const float* W_at1 = (const float*)d_in[4];
    const float* b_at1 = (const float*)d_in[5];
    const float* W_at2 = (const float*)d_in[6];
    const float* b_at2 = (const float*)d_in[7];
    const float* W_at3 = (const float*)d_in[8];
    const float* b_at3 = (const float*)d_in[9];
    const float* W_agg = (const float*)d_in[10];
    const float* b_agg = (const float*)d_in[11];
    const float* W_g1  = (const float*)d_in[12];
    const float* b_g1  = (const float*)d_in[13];
    const float* W_g2  = (const float*)d_in[14];
    const float* b_g2  = (const float*)d_in[15];
    const float* W_q   = (const float*)d_in[16];
    const float* b_q   = (const float*)d_in[17];
    const float* W_k   = (const float*)d_in[18];
    const float* b_k   = (const float*)d_in[19];
    const float* W_v   = (const float*)d_in[20];
    const float* b_v   = (const float*)d_in[21];
    float* out = (float*)d_out;

    void *pv;
    cudaGetSymbolAddress(&pv, g_part);     float*    p_part   = (float*)pv;
    cudaGetSymbolAddress(&pv, g_xw);       float*    p_xw     = (float*)pv;
    cudaGetSymbolAddress(&pv, g_x16);      uint2*    p_x16    = (uint2*)pv;
    cudaGetSymbolAddress(&pv, g_adj16);    uint2*    p_adj16  = (uint2*)pv;
    cudaGetSymbolAddress(&pv, g_xwT16);    uint2*    p_xwT16  = (uint2*)pv;
    cudaGetSymbolAddress(&pv, g_h16);      uint2*    p_h16    = (uint2*)pv;
    cudaGetSymbolAddress(&pv, g_Wg1T16);   uint2*    p_Wg1T   = (uint2*)pv;
    cudaGetSymbolAddress(&pv, g_WqT16);    uint2*    p_WqT    = (uint2*)pv;
    cudaGetSymbolAddress(&pv, g_WkT16);    uint2*    p_WkT    = (uint2*)pv;
    cudaGetSymbolAddress(&pv, g_WvT16);    uint2*    p_WvT    = (uint2*)pv;
    cudaGetSymbolAddress(&pv, g_Q);        float*    p_Q      = (float*)pv;
    cudaGetSymbolAddress(&pv, g_K);        float*    p_K      = (float*)pv;
    cudaGetSymbolAddress(&pv, g_V);        float*    p_V      = (float*)pv;
    cudaGetSymbolAddress(&pv, g_Q16);      uint32_t* p_Q16    = (uint32_t*)pv;
    cudaGetSymbolAddress(&pv, g_K16);      uint32_t* p_K16    = (uint32_t*)pv;
    cudaGetSymbolAddress(&pv, g_cand_cnt); int*      p_cnt    = (int*)pv;

    const int SMEM_GEMM = (2 * 128 * 16 + 2 * 256 * 16) * 8;     // 98304 B
    const int SMEM_QK   = (2 * 128 * QKST + 2 * 256 * QKST) * 4; // 61440 B
    cudaFuncSetAttribute(mma_split, cudaFuncAttributeMaxDynamicSharedMemorySize, SMEM_GEMM);
    cudaFuncSetAttribute(mma_qkv, cudaFuncAttributeMaxDynamicSharedMemorySize, SMEM_GEMM);
    cudaFuncSetAttribute(mma_qk, cudaFuncAttributeMaxDynamicSharedMemorySize, SMEM_QK);

    // reset candidate counters (graph-capturable)
    cudaMemsetAsync(p_cnt, 0, NN * sizeof(int));

    // small conversions (independent of gating path)
    cvt_rm_kernel<<<NN * NFEAT / 4 / 256, 256>>>(x, p_x16, NN * NFEAT / 4);
    cvt_tr_kernel<<<dim3(NFEAT / 32, NHID / 32), 256>>>(W_g1, p_Wg1T, NFEAT, NHID);
    cvt_tr_kernel<<<dim3(NHID / 32, NHID / 32), 256>>>(W_q, p_WqT, NHID, NHID);
    cvt_tr_kernel<<<dim3(NHID / 32, NHID / 32), 256>>>(W_k, p_WkT, NHID, NHID);
    cvt_tr_kernel<<<dim3(NHID / 32, NHID / 32), 256>>>(W_v, p_WvT, NHID, NHID);

    // gating path (build_adj also emits adj16)
    z15_all_kernel<<<dim3(NN / 4, 3), 256>>>(adj0, adj1, adj2,
                                             W_at1, W_at2, W_at3,
                                             b_at1, b_at2, b_at3);
    gate_kernel<<<NN / 256, 256>>>(W_agg, b_agg, out + NN * NCLASS);
    build_adj_kernel<<<4096, 256>>>(adj0, adj1, adj2);

    // xw = x @ W_g1  (split-K=4, kLen2 = 64 uint2)
    mma_split<<<dim3(1, NN / BM, 4), NT_GEMM, SMEM_GEMM>>>(
        p_x16, NFEAT / 2, p_Wg1T, NFEAT / 2, p_part, (NFEAT / 2) / 4);
    combine_kernel<4, false, false, false><<<NN * NHID / 4 / 256, 256>>>(p_part, nullptr, p_xw, nullptr);
    cvt_tr_kernel<<<dim3(NN / 32, NHID / 32), 256>>>(p_xw, p_xwT16, NN, NHID);

    // h = relu(adj @ xw + b)  (split-K=3) -> h16 only
    mma_split<<<dim3(1, NN / BM, 3), NT_GEMM, SMEM_GEMM>>>(
        p_adj16, NN / 2, p_xwT16, NN / 2, p_part, (NN / 2) / 3);
    combine_kernel<3, true, true, true><<<NN * NHID / 4 / 256, 256>>>(p_part, b_g1, nullptr, p_h16);

    // Q, K, V batched; Q16/K16 emitted fused
    QKVArgs qa;
    qa.W[0] = p_WqT; qa.W[1] = p_WkT; qa.W[2] = p_WvT;
    qa.b[0] = b_q;   qa.b[1] = b_k;   qa.b[2] = b_v;
    qa.C[0] = p_Q;   qa.C[1] = p_K;   qa.C[2] = p_V;
    qa.C16[0] = p_Q16; qa.C16[1] = p_K16; qa.C16[2] = nullptr;
    mma_qkv<<<dim3(1, NN / BM, 3), NT_GEMM, SMEM_GEMM>>>(p_h16, qa);

    // graph-masked attention: fp16 screening -> exact sparse
    mma_qk<<<dim3(NN / BN2, NN / BM), NT_GEMM, SMEM_QK>>>(p_Q16, p_K16);
    sparse_attn_kernel<<<NN, 256>>>();

    // output head
    y_kernel<<<NN / 8, 256>>>(W_g2);
    final_kernel<<<NN / 8, 256>>>(b_g2, out);
}

// round 16
// speedup vs baseline: 1.0471x; 1.0471x over previous
#include <cuda_runtime.h>
#include <cuda_fp16.h>
#include <math.h>
#include <stdint.h>

#define NN     6144
#define NFEAT  512
#define NHID   256
#define NCLASS 16

#define BM   128
#define BN2  256
#define CCAP 256
#define NT_GEMM 512
#define GST  20          // GEMM smem row stride in uint2 (conflict-free; 16 was 8-way!)
#define QKST 20          // QK smem row stride in uint32 (conflict-free)

// ---------------- scratch (static __device__, no allocation) ----------------
__device__ __align__(16) float g_adj[(size_t)NN * NN];
__device__ __align__(16) uint2 g_adj16[(size_t)NN * (NN / 2)];   // fp16 split of adj
__device__ __align__(16) float g_z15[NN * 15];
__device__ __align__(16) float g_nz[NN * 3];
__device__ __align__(16) float g_part[(size_t)4 * NN * NHID];
__device__ __align__(16) float g_xw[NN * NHID];
__device__ __align__(16) uint2 g_x16[(size_t)NN * (NFEAT / 2)];
__device__ __align__(16) uint2 g_xwT16[(size_t)NHID * (NN / 2)];
__device__ __align__(16) uint2 g_h16[(size_t)NN * (NHID / 2)];
__device__ __align__(16) uint2 g_Wg1T16[NHID * (NFEAT / 2)];
__device__ __align__(16) uint2 g_WqT16[NHID * (NHID / 2)];
__device__ __align__(16) uint2 g_WkT16[NHID * (NHID / 2)];
__device__ __align__(16) uint2 g_WvT16[NHID * (NHID / 2)];
__device__ __align__(16) float g_Q[NN * NHID];
__device__ __align__(16) float g_K[NN * NHID];
__device__ __align__(16) float g_V[NN * NHID];
__device__ __align__(16) uint32_t g_Q16[(size_t)NN * (NHID / 2)];
__device__ __align__(16) uint32_t g_K16[(size_t)NN * (NHID / 2)];
__device__ __align__(16) float g_Xt[NN * NHID];
__device__ __align__(16) float g_Y[NN * NCLASS];
__device__ int   g_cand_cnt[NN];
__device__ int   g_cand_idx[(size_t)NN * CCAP];

// ---------------- helpers ----------------------------------------------------
__device__ __forceinline__ void cp16(uint32_t s, const void* g) {
    asm volatile("cp.async.cg.shared.global [%0], [%1], 16;" :: "r"(s), "l"(g));
}
__device__ __forceinline__ void cpcommit() { asm volatile("cp.async.commit_group;"); }
__device__ __forceinline__ void cpwait1()  { asm volatile("cp.async.wait_group 1;"); }
__device__ __forceinline__ void cpwait0()  { asm volatile("cp.async.wait_group 0;"); }

__device__ __forceinline__ uint32_t pack16(float x, float y) {
    __half2 h = __float22half2_rn(make_float2(x, y));
    return *reinterpret_cast<uint32_t*>(&h);
}
__device__ __forceinline__ void split2(float x, float y, uint32_t& hi, uint32_t& lo) {
    __half2 h = __float22half2_rn(make_float2(x, y));
    float rx = x - __half2float(__low2half(h));
    float ry = y - __half2float(__high2half(h));
    __half2 l = __float22half2_rn(make_float2(rx, ry));
    hi = *reinterpret_cast<uint32_t*>(&h);
    lo = *reinterpret_cast<uint32_t*>(&l);
}
__device__ __forceinline__ void mma16(float* c, const uint32_t* a, const uint32_t* b) {
    asm volatile(
        "mma.sync.aligned.m16n8k16.row.col.f32.f16.f16.f32 "
        "{%0,%1,%2,%3},{%4,%5,%6,%7},{%8,%9},{%0,%1,%2,%3};"
        : "+f"(c[0]), "+f"(c[1]), "+f"(c[2]), "+f"(c[3])
        : "r"(a[0]), "r"(a[1]), "r"(a[2]), "r"(a[3]), "r"(b[0]), "r"(b[1]));
}

// ---------------- z{1,2,3}: 4 rows per block, grid (NN/4, 3) ----------------
__global__ void z15_all_kernel(const float* __restrict__ a0,
                               const float* __restrict__ a1,
                               const float* __restrict__ a2,
                               const float* __restrict__ W1,
                               const float* __restrict__ W2,
                               const float* __restrict__ W3,
                               const float* __restrict__ b1,
                               const float* __restrict__ b2,
                               const float* __restrict__ b3)
{
    int i0 = blockIdx.x * 4;
    int slot = blockIdx.y;
    const float* adj = (slot == 0) ? a0 : (slot == 1) ? a1 : a2;
    const float* W   = (slot == 0) ? W1 : (slot == 1) ? W2 : W3;
    const float* b   = (slot == 0) ? b1 : (slot == 1) ? b2 : b3;
    int tid = threadIdx.x;
    float acc[5][4];
#pragma unroll
    for (int c = 0; c < 5; c++)
#pragma unroll
        for (int r = 0; r < 4; r++) acc[c][r] = 0.f;
    for (int j = tid; j < NN; j += 256) {
        const float* w = W + j * 5;
        float w0 = w[0], w1 = w[1], w2 = w[2], w3 = w[3], w4 = w[4];
#pragma unroll
        for (int r = 0; r < 4; r++) {
            float a = adj[(size_t)(i0 + r) * NN + j];
            acc[0][r] += a * w0; acc[1][r] += a * w1; acc[2][r] += a * w2;
            acc[3][r] += a * w3; acc[4][r] += a * w4;
        }
    }
    __shared__ float red[20][256];
#pragma unroll
    for (int c = 0; c < 5; c++)
#pragma unroll
        for (int r = 0; r < 4; r++) red[c * 4 + r][tid] = acc[c][r];
    __syncthreads();
    for (int s = 128; s > 0; s >>= 1) {
        if (tid < s) {
#pragma unroll
            for (int cc = 0; cc < 20; cc++) red[cc][tid] += red[cc][tid + s];
        }
        __syncthreads();
    }
    if (tid < 20) {
        int c = tid >> 2, r = tid & 3;
        g_z15[(i0 + r) * 15 + slot * 5 + c] = red[tid][0] + b[c];
    }
}

// ---------------- gate ------------------------------------------------------
__global__ void gate_kernel(const float* __restrict__ W_agg,
                            const float* __restrict__ b_agg,
                            float* __restrict__ nj_out)
{
    int i = blockIdx.x * blockDim.x + threadIdx.x;
    if (i >= NN) return;
    float z0 = b_agg[0], z1 = b_agg[1], z2 = b_agg[2];
#pragma unroll
    for (int k = 0; k < 15; k++) {
        float v = g_z15[i * 15 + k];
        z0 += v * W_agg[k * 3 + 0];
        z1 += v * W_agg[k * 3 + 1];
        z2 += v * W_agg[k * 3 + 2];
    }
    float m = fmaxf(z0, fmaxf(z1, z2));
    float e0 = expf(z0 - m), e1 = expf(z1 - m), e2 = expf(z2 - m);
    float s = e0 + e1 + e2;
    float n0 = e0 / s, n1 = e1 / s, n2 = e2 / s;
    g_nz[i * 3 + 0] = n0; g_nz[i * 3 + 1] = n1; g_nz[i * 3 + 2] = n2;
    nj_out[i * 3 + 0] = n0; nj_out[i * 3 + 1] = n1; nj_out[i * 3 + 2] = n2;
}

// ---------------- build adj (fp32 + fused fp16 split) -----------------------
__global__ void build_adj_kernel(const float* __restrict__ a0,
                                 const float* __restrict__ a1,
                                 const float* __restrict__ a2)
{
    const int total4 = NN * (NN / 4);
    int stride = gridDim.x * blockDim.x;
    for (int p = blockIdx.x * blockDim.x + threadIdx.x; p < total4; p += stride) {
        int idx = p * 4;
        int j = idx % NN;
        float4 v0 = ((const float4*)a0)[p];
        float4 v1 = ((const float4*)a1)[p];
        float4 v2 = ((const float4*)a2)[p];
        float4 r;
        r.x = g_nz[(j + 0) * 3 + 0] * v0.x + g_nz[(j + 0) * 3 + 1] * v1.x + g_nz[(j + 0) * 3 + 2] * v2.x;
        r.y = g_nz[(j + 1) * 3 + 0] * v0.y + g_nz[(j + 1) * 3 + 1] * v1.y + g_nz[(j + 1) * 3 + 2] * v2.y;
        r.z = g_nz[(j + 2) * 3 + 0] * v0.z + g_nz[(j + 2) * 3 + 1] * v1.z + g_nz[(j + 2) * 3 + 2] * v2.z;
        r.w = g_nz[(j + 3) * 3 + 0] * v0.w + g_nz[(j + 3) * 3 + 1] * v1.w + g_nz[(j + 3) * 3 + 2] * v2.w;
        ((float4*)g_adj)[p] = r;
        uint32_t h0, l0, h1, l1;
        split2(r.x, r.y, h0, l0);
        split2(r.z, r.w, h1, l1);
        ((uint4*)g_adj16)[p] = make_uint4(h0, l0, h1, l1);
    }
}

// ---------------- convert row-major fp32 -> [M][K/2] uint2 split ------------
__global__ void cvt_rm_kernel(const float* __restrict__ src, uint2* __restrict__ dst,
                              int total4)
{
    int p4 = blockIdx.x * 256 + threadIdx.x;
    if (p4 >= total4) return;
    float4 v = ((const float4*)src)[p4];
    uint32_t h0, l0, h1, l1;
    split2(v.x, v.y, h0, l0);
    split2(v.z, v.w, h1, l1);
    ((uint4*)dst)[p4] = make_uint4(h0, l0, h1, l1);
}

// ---------------- convert [K][N] fp32 -> [N][K/2] uint2 split (transpose) ---
// smem tile stride 33 floats: SCALAR smem stores (float4 would be misaligned).
__global__ void cvt_tr_kernel(const float* __restrict__ src, uint2* __restrict__ dst,
                              int K, int N)
{
    __shared__ float s[32][33];
    int k0 = blockIdx.x * 32, n0 = blockIdx.y * 32;
    int t = threadIdx.x;
    int r = t >> 3, c4 = (t & 7) * 4;
    float4 v = *(const float4*)&src[(size_t)(k0 + r) * N + n0 + c4];
    s[r][c4 + 0] = v.x;
    s[r][c4 + 1] = v.y;
    s[r][c4 + 2] = v.z;
    s[r][c4 + 3] = v.w;
    __syncthreads();
    int n = t >> 3, kq = (t & 7) * 2;
#pragma unroll
    for (int j = 0; j < 2; j++) {
        int k2 = kq + j;
        uint32_t hi, lo;
        split2(s[2 * k2][n], s[2 * k2 + 1][n], hi, lo);
        dst[(size_t)(n0 + n) * (K / 2) + (k0 >> 1) + k2] = make_uint2(hi, lo);
    }
}

// ---------------- fp16 pre-split GEMM: 512 thr, block 128x256 ---------------
// A16 [M][ldA2] uint2(hi,lo); B16 [N][ldB2] uint2; chunk = 16 uint2 of k.
// smem rows padded to GST=20 uint2: fragment LDS.64 conflict-free.
template<bool BIAS, bool RELU>
__device__ __forceinline__ void gemm_body16(const uint2* __restrict__ A16, int ldA2,
                                            const uint2* __restrict__ B16, int ldB2,
                                            int kOff2, int nIter,
                                            float* __restrict__ C,
                                            uint32_t* __restrict__ C16,
                                            int Nc, const float* __restrict__ bias)
{
    extern __shared__ uint2 sm2[];
    uint2* As = sm2;                     // [2][128][GST]
    uint2* Bs = sm2 + 2 * 128 * GST;     // [2][256][GST]

    int tid = threadIdx.x, lane = tid & 31, warp = tid >> 5;
    int g = lane >> 2, tig = lane & 3;
    int wm = (warp >> 2) * 32;
    int wn = (warp & 3) * 64;
    int rowBase = blockIdx.y * BM, colBase = blockIdx.x * BN2;

    float c[2][8][4];
#pragma unroll
    for (int mt = 0; mt < 2; mt++)
#pragma unroll
        for (int nt = 0; nt < 8; nt++)
#pragma unroll
            for (int r = 0; r < 4; r++) c[mt][nt][r] = 0.f;

    int am = tid >> 2, aq2 = (tid & 3) * 4;   // A: 128 rows x 16 uint2 (in 20-row)
    int bn = tid >> 1, bq2 = (tid & 1) * 8;   // B: 256 rows x 16 uint2

    auto loadChunk = [&](int it, int buf) {
        uint2* Asb = As + buf * 128 * GST;
        uint2* Bsb = Bs + buf * 256 * GST;
        const uint2* Ag = A16 + (size_t)(rowBase + am) * ldA2 + kOff2 + it * 16 + aq2;
        cp16((uint32_t)__cvta_generic_to_shared(Asb + am * GST + aq2), Ag);
        cp16((uint32_t)__cvta_generic_to_shared(Asb + am * GST + aq2 + 2), Ag + 2);
        const uint2* Bg = B16 + (size_t)(colBase + bn) * ldB2 + kOff2 + it * 16 + bq2;
#pragma unroll
        for (int i = 0; i < 4; i++)
            cp16((uint32_t)__cvta_generic_to_shared(Bsb + bn * GST + bq2 + 2 * i), Bg + 2 * i);
        cpcommit();
    };

    loadChunk(0, 0);
    for (int it = 0; it < nIter; ++it) {
        int buf = it & 1;
        if (it + 1 < nIter) { loadChunk(it + 1, buf ^ 1); cpwait1(); }
        else cpwait0();
        __syncthreads();
        const uint2* Asb = As + buf * 128 * GST;
        const uint2* Bsb = Bs + buf * 256 * GST;
#pragma unroll
        for (int ks = 0; ks < 2; ks++) {
            int kb2 = ks * 8;
            uint32_t ah[2][4], al[2][4];
#pragma unroll
            for (int mt = 0; mt < 2; mt++) {
                int r0 = wm + mt * 16 + g;
                uint2 q0 = Asb[r0 * GST + kb2 + tig];
                uint2 q1 = Asb[(r0 + 8) * GST + kb2 + tig];
                uint2 q2 = Asb[r0 * GST + kb2 + tig + 4];
                uint2 q3 = Asb[(r0 + 8) * GST + kb2 + tig + 4];
                ah[mt][0] = q0.x; al[mt][0] = q0.y;
                ah[mt][1] = q1.x; al[mt][1] = q1.y;
                ah[mt][2] = q2.x; al[mt][2] = q2.y;
                ah[mt][3] = q3.x; al[mt][3] = q3.y;
            }
#pragma unroll
            for (int h2 = 0; h2 < 2; h2++) {
                uint32_t bh[4][2], bl[4][2];
#pragma unroll
                for (int nl = 0; nl < 4; nl++) {
                    int nc = wn + (h2 * 4 + nl) * 8 + g;
                    uint2 u0 = Bsb[nc * GST + kb2 + tig];
                    uint2 u1 = Bsb[nc * GST + kb2 + tig + 4];
                    bh[nl][0] = u0.x; bl[nl][0] = u0.y;
                    bh[nl][1] = u1.x; bl[nl][1] = u1.y;
                }
#pragma unroll
                for (int mt = 0; mt < 2; mt++)
#pragma unroll
                    for (int nl = 0; nl < 4; nl++) {
                        float* cc = c[mt][h2 * 4 + nl];
                        mma16(cc, ah[mt], bh[nl]);
                        mma16(cc, ah[mt], bl[nl]);
                        mma16(cc, al[mt], bh[nl]);
                    }
            }
        }
        __syncthreads();
    }

#pragma unroll
    for (int mt = 0; mt < 2; mt++) {
        int row = rowBase + wm + mt * 16 + g;
#pragma unroll
        for (int nt = 0; nt < 8; nt++) {
            int col = colBase + wn + nt * 8 + 2 * tig;
            float v0 = c[mt][nt][0], v1 = c[mt][nt][1];
            float v2 = c[mt][nt][2], v3 = c[mt][nt][3];
            if (BIAS) {
                float bb0 = bias[col], bb1 = bias[col + 1];
                v0 += bb0; v1 += bb1; v2 += bb0; v3 += bb1;
            }
            if (RELU) {
                v0 = fmaxf(v0, 0.f); v1 = fmaxf(v1, 0.f);
                v2 = fmaxf(v2, 0.f); v3 = fmaxf(v3, 0.f);
            }
            *(float2*)(C + (size_t)row * Nc + col) = make_float2(v0, v1);
            *(float2*)(C + (size_t)(row + 8) * Nc + col) = make_float2(v2, v3);
            if (C16) {
                C16[(size_t)row * (Nc / 2) + col / 2] = pack16(v0, v1);
                C16[(size_t)(row + 8) * (Nc / 2) + col / 2] = pack16(v2, v3);
            }
        }
    }
}

// split-K GEMM into partials
__global__ void __launch_bounds__(NT_GEMM)
mma_split(const uint2* __restrict__ A16, int ldA2,
          const uint2* __restrict__ B16, int ldB2,
          float* __restrict__ P, int kLen2)
{
    int kOff2 = blockIdx.z * kLen2;
    gemm_body16<false, false>(A16, ldA2, B16, ldB2, kOff2, kLen2 / 16,
                              P + (size_t)blockIdx.z * NN * NHID, nullptr, NHID, nullptr);
}

// batched QKV: blockIdx.z selects weight/bias/outputs
struct QKVArgs { const uint2* W[3]; const float* b[3]; float* C[3]; uint32_t* C16[3]; };
__global__ void __launch_bounds__(NT_GEMM)
mma_qkv(const uint2* __restrict__ A16, QKVArgs args)
{
    int z = blockIdx.z;
    gemm_body16<true, false>(A16, NHID / 2, args.W[z], NHID / 2, 0, (NHID / 2) / 16,
                             args.C[z], args.C16[z], NHID, args.b[z]);
}

// ---------------- combine split-K partials (+bias)(+relu)(+fp16 out) --------
template<int NP, bool BIAS, bool RELU, bool OUT16>
__global__ void combine_kernel(const float* __restrict__ P,
                               const float* __restrict__ bias,
                               float* __restrict__ out,
                               uint2* __restrict__ out16)
{
    int p4 = blockIdx.x * 256 + threadIdx.x;
    float4 v = ((const float4*)P)[p4];
#pragma unroll
    for (int z = 1; z < NP; z++) {
        float4 b = ((const float4*)(P + (size_t)z * NN * NHID))[p4];
        v.x += b.x; v.y += b.y; v.z += b.z; v.w += b.w;
    }
    if (BIAS) {
        int n = (p4 & 63) * 4;
        float4 bb = *(const float4*)(bias + n);
        v.x += bb.x; v.y += bb.y; v.z += bb.z; v.w += bb.w;
    }
    if (RELU) {
        v.x = fmaxf(v.x, 0.f); v.y = fmaxf(v.y, 0.f);
        v.z = fmaxf(v.z, 0.f); v.w = fmaxf(v.w, 0.f);
    }
    if (OUT16) {
        uint32_t h0, l0, h1, l1;
        split2(v.x, v.y, h0, l0);
        split2(v.z, v.w, h1, l1);
        ((uint4*)out16)[p4] = make_uint4(h0, l0, h1, l1);
    } else {
        ((float4*)out)[p4] = v;
    }
}

// ---------------- single-fp16 QK^T screening (pre-packed Q16/K16) -----------
__global__ void __launch_bounds__(NT_GEMM)
mma_qk(const uint32_t* __restrict__ Q16, const uint32_t* __restrict__ K16)
{
    extern __shared__ uint32_t sm1[];
    uint32_t* As = sm1;                     // [2][128][QKST]
    uint32_t* Ks = sm1 + 2 * 128 * QKST;    // [2][256][QKST]

    int tid = threadIdx.x, lane = tid & 31, warp = tid >> 5;
    int g = lane >> 2, tig = lane & 3;
    int wm = (warp >> 2) * 32;
    int wn = (warp & 3) * 64;
    int rowBase = blockIdx.y * BM, colBase = blockIdx.x * BN2;

    float c[2][8][4];
#pragma unroll
    for (int mt = 0; mt < 2; mt++)
#pragma unroll
        for (int nt = 0; nt < 8; nt++)
#pragma unroll
            for (int r = 0; r < 4; r++) c[mt][nt][r] = 0.f;

    int am = tid >> 2, aq = (tid & 3) * 4;
    int bn = tid >> 1, bq = (tid & 1) * 8;

    auto loadChunk = [&](int it, int buf) {
        uint32_t* Asb = As + buf * 128 * QKST;
        uint32_t* Ksb = Ks + buf * 256 * QKST;
        cp16((uint32_t)__cvta_generic_to_shared(Asb + am * QKST + aq),
             Q16 + (size_t)(rowBase + am) * (NHID / 2) + it * 16 + aq);
        const uint32_t* Kg = K16 + (size_t)(colBase + bn) * (NHID / 2) + it * 16 + bq;
        cp16((uint32_t)__cvta_generic_to_shared(Ksb + bn * QKST + bq), Kg);
        cp16((uint32_t)__cvta_generic_to_shared(Ksb + bn * QKST + bq + 4), Kg + 4);
        cpcommit();
    };

    const int nIter = (NHID / 2) / 16;   // 8
    loadChunk(0, 0);
    for (int it = 0; it < nIter; ++it) {
        int buf = it & 1;
        if (it + 1 < nIter) { loadChunk(it + 1, buf ^ 1); cpwait1(); }
        else cpwait0();
        __syncthreads();
        const uint32_t* Asb = As + buf * 128 * QKST;
        const uint32_t* Ksb = Ks + buf * 256 * QKST;
#pragma unroll
        for (int ks = 0; ks < 2; ks++) {
            int kb = ks * 8;
            uint32_t ah[2][4];
#pragma unroll
            for (int mt = 0; mt < 2; mt++) {
                int r0 = wm + mt * 16 + g;
                ah[mt][0] = Asb[r0 * QKST + kb + tig];
                ah[mt][1] = Asb[(r0 + 8) * QKST + kb + tig];
                ah[mt][2] = Asb[r0 * QKST + kb + tig + 4];
                ah[mt][3] = Asb[(r0 + 8) * QKST + kb + tig + 4];
            }
#pragma unroll
            for (int h2 = 0; h2 < 2; h2++) {
                uint32_t bh[4][2];
#pragma unroll
                for (int nl = 0; nl < 4; nl++) {
                    int nc = wn + (h2 * 4 + nl) * 8 + g;
                    bh[nl][0] = Ksb[nc * QKST + kb + tig];
                    bh[nl][1] = Ksb[nc * QKST + kb + tig + 4];
                }
#pragma unroll
                for (int mt = 0; mt < 2; mt++)
#pragma unroll
                    for (int nl = 0; nl < 4; nl++)
                        mma16(c[mt][h2 * 4 + nl], ah[mt], bh[nl]);
            }
        }
        __syncthreads();
    }

    // ---- epilogue: mask, per-row tile max, emit candidates ----
#pragma unroll
    for (int mt = 0; mt < 2; mt++) {
        int row = rowBase + wm + mt * 16 + g;
#pragma unroll
        for (int nt = 0; nt < 8; nt++) {
            int col = colBase + wn + nt * 8 + 2 * tig;
            float2 m0 = *(const float2*)(g_adj + (size_t)row * NN + col);
            float2 m1 = *(const float2*)(g_adj + (size_t)(row + 8) * NN + col);
            c[mt][nt][0] *= m0.x; c[mt][nt][1] *= m0.y;
            c[mt][nt][2] *= m1.x; c[mt][nt][3] *= m1.y;
        }
    }
    float lm0[2], lm1[2];
#pragma unroll
    for (int mt = 0; mt < 2; mt++) {
        float a = -1e30f, b = -1e30f;
#pragma unroll
        for (int nt = 0; nt < 8; nt++) {
            a = fmaxf(a, fmaxf(c[mt][nt][0], c[mt][nt][1]));
            b = fmaxf(b, fmaxf(c[mt][nt][2], c[mt][nt][3]));
        }
        lm0[mt] = a; lm1[mt] = b;
    }
#pragma unroll
    for (int mt = 0; mt < 2; mt++) {
        lm0[mt] = fmaxf(lm0[mt], __shfl_xor_sync(0xffffffffu, lm0[mt], 1));
        lm0[mt] = fmaxf(lm0[mt], __shfl_xor_sync(0xffffffffu, lm0[mt], 2));
        lm1[mt] = fmaxf(lm1[mt], __shfl_xor_sync(0xffffffffu, lm1[mt], 1));
        lm1[mt] = fmaxf(lm1[mt], __shfl_xor_sync(0xffffffffu, lm1[mt], 2));
    }
    float* smax = (float*)sm1;     // reuse: [128][4]
    int q = warp & 3;
    if (tig == 0) {
#pragma unroll
        for (int mt = 0; mt < 2; mt++) {
            smax[(wm + mt * 16 + g) * 4 + q] = lm0[mt];
            smax[(wm + mt * 16 + 8 + g) * 4 + q] = lm1[mt];
        }
    }
    __syncthreads();
#pragma unroll
    for (int mt = 0; mt < 2; mt++) {
#pragma unroll
        for (int half = 0; half < 2; half++) {
            int rl = wm + mt * 16 + half * 8 + g;
            float tm = fmaxf(fmaxf(smax[rl * 4 + 0], smax[rl * 4 + 1]),
                             fmaxf(smax[rl * 4 + 2], smax[rl * 4 + 3]));
            float thr = tm - 120.0f;
            int rowG = rowBase + rl;
#pragma unroll
            for (int nt = 0; nt < 8; nt++) {
#pragma unroll
                for (int j = 0; j < 2; j++) {
                    float v = c[mt][nt][half * 2 + j];
                    if (v > thr) {
                        int slot = atomicAdd(&g_cand_cnt[rowG], 1);
                        if (slot < CCAP)
                            g_cand_idx[(size_t)rowG * CCAP + slot] =
                                colBase + wn + nt * 8 + 2 * tig + j;
                    }
                }
            }
        }
    }
}

// ---------------- sparse attention: exact recompute + softmax + apply -------
__global__ void sparse_attn_kernel()
{
    __shared__ float qrow[NHID];
    __shared__ int   ci[CCAP];
    __shared__ float cv[CCAP];
    __shared__ float red[256];
    __shared__ float sw[CCAP];
    __shared__ int   sidx[CCAP];
    __shared__ int   scnt;
    int i = blockIdx.x;
    int tid = threadIdx.x;
    int warp = tid >> 5, lane = tid & 31;
    int cnt = g_cand_cnt[i];
    if (cnt > CCAP) cnt = CCAP;
    qrow[tid] = g_Q[(size_t)i * NHID + tid];
    if (tid < cnt) ci[tid] = g_cand_idx[(size_t)i * CCAP + tid];
    if (tid == 0) scnt = 0;
    __syncthreads();
    for (int c = warp; c < cnt; c += 8) {
        const float* kr = g_K + (size_t)ci[c] * NHID;
        float s = 0.f;
#pragma unroll
        for (int k = lane; k < NHID; k += 32) s += qrow[k] * kr[k];
#pragma unroll
        for (int o = 16; o > 0; o >>= 1) s += __shfl_xor_sync(0xffffffffu, s, o);
        if (lane == 0) cv[c] = s * g_adj[(size_t)i * NN + ci[c]];
    }
    __syncthreads();
    float m = (tid < cnt) ? cv[tid] : -1e30f;
    red[tid] = m;
    __syncthreads();
    for (int s = 128; s > 0; s >>= 1) {
        if (tid < s) red[tid] = fmaxf(red[tid], red[tid + s]);
        __syncthreads();
    }
    m = red[0];
    __syncthreads();
    float e = (tid < cnt) ? expf(cv[tid] - m) : 0.f;
    red[tid] = e;
    __syncthreads();
    for (int s = 128; s > 0; s >>= 1) {
        if (tid < s) red[tid] += red[tid + s];
        __syncthreads();
    }
    float inv = 1.0f / red[0];
    if (tid < cnt && cv[tid] - m > -25.f) {
        int sl = atomicAdd(&scnt, 1);
        sw[sl] = expf(cv[tid] - m) * inv;
        sidx[sl] = ci[tid];
    }
    __syncthreads();
    int ns = scnt;
    float acc = 0.f;
    for (int e2 = 0; e2 < ns; e2++)
        acc += sw[e2] * g_V[(size_t)sidx[e2] * NHID + tid];
    g_Xt[(size_t)i * NHID + tid] = fmaxf(acc, 0.f);
}

// ---------------- Y = Xt @ W_g2  (warp per row) -----------------------------
__global__ void y_kernel(const float* __restrict__ Wg2)
{
    __shared__ float Ws[NHID * NCLASS];
    int tid = threadIdx.x;
    for (int t = tid; t < NHID * NCLASS / 4; t += 256)
        ((float4*)Ws)[t] = ((const float4*)Wg2)[t];
    __syncthreads();
    int warp = tid >> 5, lane = tid & 31;
    int i = blockIdx.x * 8 + warp;
    float acc[16];
#pragma unroll
    for (int c = 0; c < 16; c++) acc[c] = 0.f;
    const float* xr = g_Xt + (size_t)i * NHID;
    for (int g = lane; g < NHID; g += 32) {
        float x = xr[g];
#pragma unroll
        for (int c = 0; c < 16; c++) acc[c] += x * Ws[g * 16 + c];
    }
#pragma unroll
    for (int c = 0; c < 16; c++)
#pragma unroll
        for (int o = 16; o > 0; o >>= 1)
            acc[c] += __shfl_xor_sync(0xffffffffu, acc[c], o);
    if (lane < 16) g_Y[i * 16 + lane] = acc[lane];
}

// ---------------- out = softmax(adj @ Y + b_g2)  (warp per row) -------------
__global__ void final_kernel(const float* __restrict__ b_g2,
                             float* __restrict__ out)
{
    __shared__ float Ys[512 * 16];
    int tid = threadIdx.x;
    int warp = tid >> 5, lane = tid & 31;
    int i = blockIdx.x * 8 + warp;
    float acc[16];
#pragma unroll
    for (int c = 0; c < 16; c++) acc[c] = 0.f;
    const float* arow = g_adj + (size_t)i * NN;
    for (int j0 = 0; j0 < NN; j0 += 512) {
        __syncthreads();
        for (int t = tid; t < 512 * 16 / 4; t += 256)
            ((float4*)Ys)[t] = ((const float4*)(g_Y + j0 * 16))[t];
        __syncthreads();
        for (int jj = lane; jj < 512; jj += 32) {
            float a = arow[j0 + jj];
#pragma unroll
            for (int c = 0; c < 16; c++) acc[c] += a * Ys[jj * 16 + c];
        }
    }
#pragma unroll
    for (int c = 0; c < 16; c++)
#pragma unroll
        for (int o = 16; o > 0; o >>= 1)
            acc[c] += __shfl_xor_sync(0xffffffffu, acc[c], o);
    if (lane == 0) {
        float z[16], m = -1e30f;
#pragma unroll
        for (int c = 0; c < 16; c++) { z[c] = acc[c] + b_g2[c]; m = fmaxf(m, z[c]); }
        float s = 0.f, e[16];
#pragma unroll
        for (int c = 0; c < 16; c++) { e[c] = expf(z[c] - m); s += e[c]; }
#pragma unroll
        for (int c = 0; c < 16; c++) out[i * 16 + c] = e[c] / s;
    }
}

// ---------------- launcher ---------------------------------------------------
extern "C" void kernel_launch(void* const* d_in, const int* in_sizes, int n_in,
                              void* d_out, int out_size)
{
    const float* adj0  = (const float*)d_in[0];
    const float* adj1  = (const float*)d_in[1];
    const float* adj2  = (const float*)d_in[2];
    const float* x     = (const float*)d_in[3];
    const float* W_at1 = (const float*)d_in[4];
    const float* b_at1 = (const float*)d_in[5];
    const float* W_at2 = (const float*)d_in[6];
    const float* b_at2 = (const float*)d_in[7];
    const float* W_at3 = (const float*)d_in[8];
    const float* b_at3 = (const float*)d_in[9];
    const float* W_agg = (const float*)d_in[10];
    const float* b_agg = (const float*)d_in[11];
    const float* W_g1  = (const float*)d_in[12];
    const float* b_g1  = (const float*)d_in[13];
    const float* W_g2  = (const float*)d_in[14];
    const float* b_g2  = (const float*)d_in[15];
    const float* W_q   = (const float*)d_in[16];
    const float* b_q   = (const float*)d_in[17];
    const float* W_k   = (const float*)d_in[18];
    const float* b_k   = (const float*)d_in[19];
    const float* W_v   = (const float*)d_in[20];
    const float* b_v   = (const float*)d_in[21];
    float* out = (float*)d_out;

    void *pv;
    cudaGetSymbolAddress(&pv, g_part);     float*    p_part   = (float*)pv;
    cudaGetSymbolAddress(&pv, g_xw);       float*    p_xw     = (float*)pv;
    cudaGetSymbolAddress(&pv, g_x16);      uint2*    p_x16    = (uint2*)pv;
    cudaGetSymbolAddress(&pv, g_adj16);    uint2*    p_adj16  = (uint2*)pv;
    cudaGetSymbolAddress(&pv, g_xwT16);    uint2*    p_xwT16  = (uint2*)pv;
    cudaGetSymbolAddress(&pv, g_h16);      uint2*    p_h16    = (uint2*)pv;
    cudaGetSymbolAddress(&pv, g_Wg1T16);   uint2*    p_Wg1T   = (uint2*)pv;
    cudaGetSymbolAddress(&pv, g_WqT16);    uint2*    p_WqT    = (uint2*)pv;
    cudaGetSymbolAddress(&pv, g_WkT16);    uint2*    p_WkT    = (uint2*)pv;
    cudaGetSymbolAddress(&pv, g_WvT16);    uint2*    p_WvT    = (uint2*)pv;
    cudaGetSymbolAddress(&pv, g_Q);        float*    p_Q      = (float*)pv;
    cudaGetSymbolAddress(&pv, g_K);        float*    p_K      = (float*)pv;
    cudaGetSymbolAddress(&pv, g_V);        float*    p_V      = (float*)pv;
    cudaGetSymbolAddress(&pv, g_Q16);      uint32_t* p_Q16    = (uint32_t*)pv;
    cudaGetSymbolAddress(&pv, g_K16);      uint32_t* p_K16    = (uint32_t*)pv;
    cudaGetSymbolAddress(&pv, g_cand_cnt); int*      p_cnt    = (int*)pv;

    const int SMEM_GEMM = (2 * 128 * GST + 2 * 256 * GST) * 8;   // 122880 B
    const int SMEM_QK   = (2 * 128 * QKST + 2 * 256 * QKST) * 4; // 61440 B
    cudaFuncSetAttribute(mma_split, cudaFuncAttributeMaxDynamicSharedMemorySize, SMEM_GEMM);
    cudaFuncSetAttribute(mma_qkv, cudaFuncAttributeMaxDynamicSharedMemorySize, SMEM_GEMM);
    cudaFuncSetAttribute(mma_qk, cudaFuncAttributeMaxDynamicSharedMemorySize, SMEM_QK);

    // reset candidate counters (graph-capturable)
    cudaMemsetAsync(p_cnt, 0, NN * sizeof(int));

    // small conversions (independent of gating path)
    cvt_rm_kernel<<<NN * NFEAT / 4 / 256, 256>>>(x, p_x16, NN * NFEAT / 4);
    cvt_tr_kernel<<<dim3(NFEAT / 32, NHID / 32), 256>>>(W_g1, p_Wg1T, NFEAT, NHID);
    cvt_tr_kernel<<<dim3(NHID / 32, NHID / 32), 256>>>(W_q, p_WqT, NHID, NHID);
    cvt_tr_kernel<<<dim3(NHID / 32, NHID / 32), 256>>>(W_k, p_WkT, NHID, NHID);
    cvt_tr_kernel<<<dim3(NHID / 32, NHID / 32), 256>>>(W_v, p_WvT, NHID, NHID);

    // gating path (build_adj also emits adj16)
    z15_all_kernel<<<dim3(NN / 4, 3), 256>>>(adj0, adj1, adj2,
                                             W_at1, W_at2, W_at3,
                                             b_at1, b_at2, b_at3);
    gate_kernel<<<NN / 256, 256>>>(W_agg, b_agg, out + NN * NCLASS);
    build_adj_kernel<<<4096, 256>>>(adj0, adj1, adj2);

    // xw = x @ W_g1  (split-K=4, kLen2 = 64 uint2)
    mma_split<<<dim3(1, NN / BM, 4), NT_GEMM, SMEM_GEMM>>>(
        p_x16, NFEAT / 2, p_Wg1T, NFEAT / 2, p_part, (NFEAT / 2) / 4);
    combine_kernel<4, false, false, false><<<NN * NHID / 4 / 256, 256>>>(p_part, nullptr, p_xw, nullptr);
    cvt_tr_kernel<<<dim3(NN / 32, NHID / 32), 256>>>(p_xw, p_xwT16, NN, NHID);

    // h = relu(adj @ xw + b)  (split-K=3) -> h16 only
    mma_split<<<dim3(1, NN / BM, 3), NT_GEMM, SMEM_GEMM>>>(
        p_adj16, NN / 2, p_xwT16, NN / 2, p_part, (NN / 2) / 3);
    combine_kernel<3, true, true, true><<<NN * NHID / 4 / 256, 256>>>(p_part, b_g1, nullptr, p_h16);

    // Q, K, V batched; Q16/K16 emitted fused
    QKVArgs qa;
    qa.W[0] = p_WqT; qa.W[1] = p_WkT; qa.W[2] = p_WvT;
    qa.b[0] = b_q;   qa.b[1] = b_k;   qa.b[2] = b_v;
    qa.C[0] = p_Q;   qa.C[1] = p_K;   qa.C[2] = p_V;
    qa.C16[0] = p_Q16; qa.C16[1] = p_K16; qa.C16[2] = nullptr;
    mma_qkv<<<dim3(1, NN / BM, 3), NT_GEMM, SMEM_GEMM>>>(p_h16, qa);

    // graph-masked attention: fp16 screening -> exact sparse
    mma_qk<<<dim3(NN / BN2, NN / BM), NT_GEMM, SMEM_QK>>>(p_Q16, p_K16);
    sparse_attn_kernel<<<NN, 256>>>();

    // output head
    y_kernel<<<NN / 8, 256>>>(W_g2);
    final_kernel<<<NN / 8, 256>>>(b_g2, out);
}